// round 17
// baseline (speedup 1.0000x reference)
#include <cuda_runtime.h>

// Problem constants
#define BQ    8192
#define NSUB  16
#define KC    1024
#define EDIM  16
#define DEPTHQ 3
#define DIMQ  256

// Output layout: [loss(1), z_q_out(B*256), onehot(B*16*1024), idx(B*16)]
#define OFF_LOSS   ((size_t)0)
#define OFF_ZQ     ((size_t)1)
#define OFF_ONEHOT ((size_t)(1 + BQ * DIMQ))
#define OFF_IDX    ((size_t)(OFF_ONEHOT + (size_t)BQ * NSUB * KC))

__device__ float g_P[(size_t)NSUB * KC * DIMQ];
__device__ int   g_idx[(size_t)BQ * NSUB * DEPTHQ];

// ---------------- packed f32x2 helpers ----------------
__device__ __forceinline__ unsigned long long pack2(float a, float b) {
    unsigned long long r;
    asm("mov.b64 %0, {%1,%2};" : "=l"(r) : "f"(a), "f"(b));
    return r;
}
__device__ __forceinline__ void fma2(unsigned long long& d, unsigned long long a, unsigned long long b) {
    asm("fma.rn.f32x2 %0, %1, %2, %0;" : "+l"(d) : "l"(a), "l"(b));
}
__device__ __forceinline__ unsigned long long fma2v(unsigned long long a, unsigned long long b, unsigned long long c) {
    unsigned long long r;
    asm("fma.rn.f32x2 %0, %1, %2, %3;" : "=l"(r) : "l"(a), "l"(b), "l"(c));
    return r;
}
__device__ __forceinline__ unsigned long long add2(unsigned long long a, unsigned long long b) {
    unsigned long long r;
    asm("add.rn.f32x2 %0, %1, %2;" : "=l"(r) : "l"(a), "l"(b));
    return r;
}
__device__ __forceinline__ void unpack2(unsigned long long v, float& lo, float& hi) {
    asm("mov.b64 {%0,%1}, %2;" : "=f"(lo), "=f"(hi) : "l"(v));
}

// ---------------- kernel 1: P precompute (+ zero loss slot) ----------------
__global__ void compute_P_kernel(const float* __restrict__ emb,
                                 const float* __restrict__ W,
                                 float* __restrict__ out) {
    if (blockIdx.x == 0 && threadIdx.x == 0) out[OFF_LOSS] = 0.0f;

    const int n  = blockIdx.x >> 6;
    const int k0 = (blockIdx.x & 63) * 16;
    const int j  = threadIdx.x;

    __shared__ float se[16 * EDIM];
    se[j] = emb[((size_t)n * KC + k0) * EDIM + j];

    float w[16];
#pragma unroll
    for (int i = 0; i < 16; i++) w[i] = W[(size_t)(n * 16 + i) * DIMQ + j];
    __syncthreads();

#pragma unroll
    for (int kk = 0; kk < 16; kk++) {
        float acc = 0.0f;
#pragma unroll
        for (int i = 0; i < 16; i++) acc = fmaf(se[kk * EDIM + i], w[i], acc);
        g_P[((size_t)n * KC + (k0 + kk)) * DIMQ + j] = acc;
    }
}

// ---------------- kernel 2: VQ search — R16 loop + tree epilogue + vector zero-fill ----------------
// grid (16 row-tiles of 512 rows, 16 n), 256 threads, 2 rows/thread, 2 blocks/SM.
#define NKP (KC / 2)
#define VQ_SMEM ((size_t)(NKP * EDIM * 8 + NKP * 8))

// Exact sequential replay of the reference argmin over the 4 scores of one
// group (ascending code order). Entry: BS = running min-s BEFORE this group;
// by monotonicity of s -> sqrt(max(s,0)), the running min-d equals
// sqrt(max(BS,0)), so it is recomputed here instead of being carried.
// Semantics identical to the R7-proven sequential update (validated R11).
#define REPLAY4(S0, S1, S2, S3, BS, BK, KB) do {                              \
    float bsRun_ = (BS);                                                      \
    float bdRun_ = sqrtf(fmaxf(bsRun_, 0.0f));                                \
    if ((S0) < bsRun_) { float dv_ = sqrtf(fmaxf((S0), 0.0f));                \
        if (dv_ < bdRun_) { bdRun_ = dv_; (BK) = (KB); }     bsRun_ = (S0); } \
    if ((S1) < bsRun_) { float dv_ = sqrtf(fmaxf((S1), 0.0f));                \
        if (dv_ < bdRun_) { bdRun_ = dv_; (BK) = (KB) + 1; } bsRun_ = (S1); } \
    if ((S2) < bsRun_) { float dv_ = sqrtf(fmaxf((S2), 0.0f));                \
        if (dv_ < bdRun_) { bdRun_ = dv_; (BK) = (KB) + 2; } bsRun_ = (S2); } \
    if ((S3) < bsRun_) { float dv_ = sqrtf(fmaxf((S3), 0.0f));                \
        if (dv_ < bdRun_) { bdRun_ = dv_; (BK) = (KB) + 3; } bsRun_ = (S3); } \
} while (0)

__global__ void __launch_bounds__(256, 2)
vq_kernel(const float* __restrict__ z,
          const float* __restrict__ emb,
          float* __restrict__ out) {
    extern __shared__ unsigned long long sm[];
    unsigned long long* pc = sm;                                 // pc[kp*16 + i] = (e[2kp][i], e[2kp+1][i])
    unsigned long long* s_esq = sm + (size_t)NKP * EDIM;         // (esq[2kp], esq[2kp+1])

    const float* pcf = (const float*)pc;  // e[k][i] at pcf[((k>>1)*16 + i)*2 + (k&1)]

    const int n = blockIdx.y;
    const int rowbase = blockIdx.x * 512;
    const int tid = threadIdx.x;

    // Build paired codebook + esq (sequential fmaf chain per code — matches ref)
    for (int kp = tid; kp < NKP; kp += 256) {
        const float* e0 = emb + ((size_t)n * KC + 2 * kp) * EDIM;
        const float* e1 = e0 + EDIM;
        float esq0 = 0.0f, esq1 = 0.0f;
        unsigned long long* m = pc + (size_t)kp * EDIM;
#pragma unroll
        for (int i = 0; i < 16; i++) {
            float v0 = __ldg(e0 + i);
            float v1 = __ldg(e1 + i);
            esq0 = fmaf(v0, v0, esq0);
            esq1 = fmaf(v1, v1, esq1);
            m[i] = pack2(v0, v1);
        }
        s_esq[kp] = pack2(esq0, esq1);
    }
    __syncthreads();

    // Two rows per thread: A = rowbase+tid, B = rowbase+256+tid.
    const int bA = rowbase + tid;
    const int bB = rowbase + 256 + tid;
    unsigned long long zdA[16], zdB[16];
    unsigned long long zsqA2, zsqB2;
    {
        const float* zA = z + (size_t)bA * DIMQ + n * EDIM;
        const float* zB = z + (size_t)bB * DIMQ + n * EDIM;
        float sA = 0.0f, sB = 0.0f;
#pragma unroll
        for (int i = 0; i < 16; i++) {
            float a = zA[i], b = zB[i];
            zdA[i] = pack2(a, a);
            zdB[i] = pack2(b, b);
            sA = fmaf(a, a, sA);
            sB = fmaf(b, b, sB);
        }
        zsqA2 = pack2(sA, sA);
        zsqB2 = pack2(sB, sB);
    }

    const unsigned long long NEG2 = 0xC0000000C0000000ull;  // (-2.f, -2.f)
    const float4 ZERO4 = make_float4(0.0f, 0.0f, 0.0f, 0.0f);

    int bkA_last = 0, bkB_last = 0;
    int zrow = 0;   // strip-mined onehot zero-fill row counter (0..511)

    for (int d = 0; d < DEPTHQ; d++) {
        float bsA = 3.4e38f, bsB = 3.4e38f;
        int bkA = 0, bkB = 0;

#pragma unroll 1
        for (int kp2 = 0; kp2 < NKP / 2; ++kp2) {
            // Strip-mined onehot zero-fill (every 8th kp2, 6 rows), vectorized:
            // row region starts at element E == 1 (mod 4); [E+3, E+1023) is
            // 16B-aligned -> one STG.128 per thread (tid<255); tid 255 writes
            // the 4 stragglers E, E+1, E+2, E+1023.
            if ((kp2 & 7) == 0) {
#pragma unroll
                for (int u = 0; u < 6; u++) {
                    if (zrow < 512) {
                        float* dst = out + OFF_ONEHOT
                                   + ((size_t)((rowbase + zrow) * NSUB + n)) * KC;
                        if (tid < 255) {
                            *(float4*)(dst + 3 + 4 * tid) = ZERO4;
                        } else {
                            dst[0] = 0.0f; dst[1] = 0.0f;
                            dst[2] = 0.0f; dst[1023] = 0.0f;
                        }
                    }
                    zrow++;
                }
            }

            const ulonglong2* mv0 = (const ulonglong2*)(pc + (size_t)(2 * kp2) * EDIM);
            const ulonglong2* mv1 = mv0 + 8;
            const ulonglong2 es2 = *((const ulonglong2*)(s_esq + 2 * kp2));

            unsigned long long aA0 = 0ull, aB0 = 0ull, aA1 = 0ull, aB1 = 0ull;
            // 4 staged sub-chunks (peak m-regs 16). Per chain, sequential
            // i = 0..15 — bit-matches the scalar fmaf chain.
#pragma unroll
            for (int c = 0; c < 4; c++) {
                ulonglong2 p0 = mv0[2 * c], q0 = mv0[2 * c + 1];
                ulonglong2 p1 = mv1[2 * c], q1 = mv1[2 * c + 1];
                const int i = 4 * c;
                fma2(aA0, zdA[i + 0], p0.x); fma2(aB0, zdB[i + 0], p0.x);
                fma2(aA1, zdA[i + 0], p1.x); fma2(aB1, zdB[i + 0], p1.x);
                fma2(aA0, zdA[i + 1], p0.y); fma2(aB0, zdB[i + 1], p0.y);
                fma2(aA1, zdA[i + 1], p1.y); fma2(aB1, zdB[i + 1], p1.y);
                fma2(aA0, zdA[i + 2], q0.x); fma2(aB0, zdB[i + 2], q0.x);
                fma2(aA1, zdA[i + 2], q1.x); fma2(aB1, zdB[i + 2], q1.x);
                fma2(aA0, zdA[i + 3], q0.y); fma2(aB0, zdB[i + 3], q0.y);
                fma2(aA1, zdA[i + 3], q1.y); fma2(aB1, zdB[i + 3], q1.y);
            }

            // per lane: s = fmaf(-2, c, zsq) + es  (bit-equal to zsq - 2c, then +es)
            unsigned long long sA02 = add2(fma2v(aA0, NEG2, zsqA2), es2.x);
            unsigned long long sB02 = add2(fma2v(aB0, NEG2, zsqB2), es2.x);
            unsigned long long sA12 = add2(fma2v(aA1, NEG2, zsqA2), es2.y);
            unsigned long long sB12 = add2(fma2v(aB1, NEG2, zsqB2), es2.y);

            float sA0l, sA0h, sA1l, sA1h, sB0l, sB0h, sB1l, sB1h;
            unpack2(sA02, sA0l, sA0h);
            unpack2(sB02, sB0l, sB0h);
            unpack2(sA12, sA1l, sA1h);
            unpack2(sB12, sB1l, sB1h);

            // Tree epilogue: a group can contribute iff its min beats the
            // running min-s (s >= bs  =>  d >= bd, no update possible).
            const float tA = fminf(fminf(sA0l, sA0h), fminf(sA1l, sA1h));
            const float tB = fminf(fminf(sB0l, sB0h), fminf(sB1l, sB1h));
            const bool cA = tA < bsA;
            const bool cB = tB < bsB;

            if (cA | cB) {
                const int kb = 4 * kp2;
                // Exact sequential replay (ascending k; sqrt-collapse ties keep
                // the LOWER index) — identical semantics to the R7 epilogue.
                if (cA) REPLAY4(sA0l, sA0h, sA1l, sA1h, bsA, bkA, kb);
                if (cB) REPLAY4(sB0l, sB0h, sB1l, sB1h, bsB, bkB, kb);
            }
            bsA = fminf(bsA, tA);
            bsB = fminf(bsB, tB);
        }

        // Residual update (one fp32 sub per component, matching ref), zsq refresh
        {
            const size_t baseA = ((size_t)(bkA >> 1) * EDIM) * 2 + (bkA & 1);
            const size_t baseB = ((size_t)(bkB >> 1) * EDIM) * 2 + (bkB & 1);
            float sA = 0.0f, sB = 0.0f;
#pragma unroll
            for (int i = 0; i < 16; i++) {
                float a, dummy, b;
                unpack2(zdA[i], a, dummy);
                unpack2(zdB[i], b, dummy);
                a = a - pcf[baseA + 2 * i];
                b = b - pcf[baseB + 2 * i];
                sA = fmaf(a, a, sA);
                sB = fmaf(b, b, sB);
                zdA[i] = pack2(a, a);
                zdB[i] = pack2(b, b);
            }
            zsqA2 = pack2(sA, sA);
            zsqB2 = pack2(sB, sB);
        }

        g_idx[((size_t)bA * NSUB + n) * DEPTHQ + d] = bkA;
        g_idx[((size_t)bB * NSUB + n) * DEPTHQ + d] = bkB;
        if (d == DEPTHQ - 1) {
            bkA_last = bkA;
            bkB_last = bkB;
            out[OFF_IDX + (size_t)bA * NSUB + n] = (float)bkA;
            out[OFF_IDX + (size_t)bB * NSUB + n] = (float)bkB;
        }
    }

    // Safety net (zrow reaches 576 >= 512 inside the loops; normally no-op)
    for (; zrow < 512; zrow++) {
        float* dst = out + OFF_ONEHOT + ((size_t)((rowbase + zrow) * NSUB + n)) * KC + tid;
        dst[0] = 0.0f; dst[256] = 0.0f; dst[512] = 0.0f; dst[768] = 0.0f;
    }

    // All zero-fills precede this barrier; the single ones after.
    __syncthreads();
    out[OFF_ONEHOT + ((size_t)bA * NSUB + n) * KC + bkA_last] = 1.0f;
    out[OFF_ONEHOT + ((size_t)bB * NSUB + n) * KC + bkB_last] = 1.0f;
}

// ---------------- kernel 3: z_q gather + z_q_out + loss ----------------
__global__ void gather_out_kernel(const float* __restrict__ z,
                                  const float* __restrict__ bias,
                                  float* __restrict__ out) {
    const int b = blockIdx.x;
    const int j = threadIdx.x;
    __shared__ int sidx[48];
    __shared__ float sred[8];

    if (j < 48) sidx[j] = g_idx[(size_t)b * 48 + j];
    __syncthreads();

    float acc = 0.0f;
#pragma unroll
    for (int n = 0; n < NSUB; n++) {
#pragma unroll
        for (int d = 0; d < DEPTHQ; d++) {
            const int k = sidx[n * 3 + d];
            acc += g_P[(((size_t)n << 10) + k) * DIMQ + j];
        }
    }
    const float zq = acc * (1.0f / 3.0f) + bias[j];
    const float zv = z[(size_t)b * DIMQ + j];
    const float diff = zq - zv;
    out[OFF_ZQ + (size_t)b * DIMQ + j] = zv + diff;

    float p = diff * diff;
#pragma unroll
    for (int off = 16; off > 0; off >>= 1) p += __shfl_down_sync(0xffffffffu, p, off);
    if ((j & 31) == 0) sred[j >> 5] = p;
    __syncthreads();
    if (j == 0) {
        float s = 0.0f;
#pragma unroll
        for (int i = 0; i < 8; i++) s += sred[i];
        atomicAdd(out + OFF_LOSS, s * (1.25f / (float)(BQ * DIMQ)));
    }
}

// ---------------- launcher ----------------
extern "C" void kernel_launch(void* const* d_in, const int* in_sizes, int n_in,
                              void* d_out, int out_size) {
    const float* z    = (const float*)d_in[0];
    const float* emb  = (const float*)d_in[1];
    const float* W    = (const float*)d_in[2];
    const float* bias = (const float*)d_in[3];
    float* out = (float*)d_out;

    (void)in_sizes; (void)n_in; (void)out_size;

    // vq first (independent of P) so ncu's sampled launch lands on vq.
    cudaFuncSetAttribute(vq_kernel, cudaFuncAttributeMaxDynamicSharedMemorySize, (int)VQ_SMEM);
    vq_kernel<<<dim3(16, 16), 256, VQ_SMEM>>>(z, emb, out);

    compute_P_kernel<<<1024, 256>>>(emb, W, out);

    gather_out_kernel<<<BQ, 256>>>(z, bias, out);
}